// round 12
// baseline (speedup 1.0000x reference)
#include <cuda_runtime.h>
#include <cuda_fp16.h>
#include <math.h>
#include <stdint.h>

#define N_NODES 50000
#define IN_DIM  256
#define OUT_DIM 128
#define T_ROWS  4096
#define N_EDGES 262144
#define CAP     256
#define LRELU_ALPHA 0.2f
#define PAD 72   // fp16 elements per smem row (144B): conflict-free ldmatrix
#define HSZ 512  // dedup hash table slots (power of 2)
#define GEMM_CTAS ((N_NODES + 127) / 128)   // 391

// ---- scratch (static __device__ globals: allocation-free) ----
__device__ float g_h[(size_t)N_NODES * OUT_DIM];   // 25.6 MB
__device__ float g_s1[N_NODES];
__device__ float g_s2[N_NODES];
__device__ int   g_cnt[T_ROWS];                    // zero-init at load; row_kernel re-zeroes
__device__ int   g_bucket[T_ROWS * CAP];
__device__ int   g_bsrc[T_ROWS * CAP];
__device__ int   g_bdst[T_ROWS * CAP];

// ---------------- helpers ----------------
__device__ __forceinline__ uint32_t smem_u32(const void* p) {
    uint32_t a;
    asm("{ .reg .u64 t; cvta.to.shared.u64 t, %1; cvt.u32.u64 %0, t; }" : "=r"(a) : "l"(p));
    return a;
}
__device__ __forceinline__ void ldmx4(uint32_t (&r)[4], uint32_t addr) {
    asm volatile("ldmatrix.sync.aligned.m8n8.x4.shared.b16 {%0,%1,%2,%3}, [%4];"
                 : "=r"(r[0]), "=r"(r[1]), "=r"(r[2]), "=r"(r[3]) : "r"(addr));
}
__device__ __forceinline__ void mma16816(float (&c)[4], const uint32_t (&a)[4],
                                         const uint32_t* b) {
    asm volatile("mma.sync.aligned.m16n8k16.row.col.f32.f16.f16.f32 "
                 "{%0,%1,%2,%3}, {%4,%5,%6,%7}, {%8,%9}, {%0,%1,%2,%3};"
                 : "+f"(c[0]), "+f"(c[1]), "+f"(c[2]), "+f"(c[3])
                 : "r"(a[0]), "r"(a[1]), "r"(a[2]), "r"(a[3]), "r"(b[0]), "r"(b[1]));
}

// SMEM layout (bytes)
#define SM_AH    0                     // 18432
#define SM_AL    18432                 // 18432
#define SM_B     36864                 // 18432 (single buffer, refilled per chunk)
#define SM_AVEC  55296                 // 256 floats
#define SM_S1B   56320                 // 128 floats
#define SM_S2B   56832                 // 128 floats
#define SMEM_TOTAL 57344

// =====================================================================
// 1) HMMA GEMM: h = F@W, fp16 2-pass (A hi+lo; B=fp16(W)), fused s1/s2.
//    Edge bucketing fused into the prologue (grid-stride over E).
// =====================================================================
__global__ void __launch_bounds__(256) gemm_mma_kernel(const float* __restrict__ F,
                                                       const float* __restrict__ W,
                                                       const float* __restrict__ a,
                                                       const void* __restrict__ adj_raw,
                                                       const void* __restrict__ tgt_raw) {
    extern __shared__ char smem[];
    __shared__ int s_is64;
    const uint32_t sb = smem_u32(smem);
    const int tid  = threadIdx.x;
    const int wid  = tid >> 5;
    const int lane = tid & 31;
    const int warp_m = wid & 1;
    const int warp_n = wid >> 1;
    const int row0 = blockIdx.x * 128;

    // ---- fused edge bucketing prologue ----
    if (tid < 32) {
        const int v = ((const int*)adj_raw)[2 * tid + 1];
        const uint32_t bal = __ballot_sync(0xffffffffu, v == 0);
        if (tid == 0) s_is64 = (bal == 0xffffffffu);
    }
    __syncthreads();
    {
        const int is64 = s_is64;
        for (int i = blockIdx.x * 256 + tid; i < N_EDGES; i += GEMM_CTAS * 256) {
            int t, sr, ds;
            if (is64) {
                t  = (int)((const long long*)tgt_raw)[i];
                sr = (int)((const long long*)adj_raw)[i];
                ds = (int)((const long long*)adj_raw)[N_EDGES + i];
            } else {
                t  = ((const int*)tgt_raw)[i];
                sr = ((const int*)adj_raw)[i];
                ds = ((const int*)adj_raw)[N_EDGES + i];
            }
            const int p = atomicAdd(&g_cnt[t], 1);
            if (p < CAP) {
                const int slot = t * CAP + p;
                g_bucket[slot] = i;
                g_bsrc[slot]   = sr;
                g_bdst[slot]   = ds;
            }
        }
    }

    // ---- stage a vector, zero s1/s2 partials ----
    {
        float* avec = (float*)(smem + SM_AVEC);
        avec[tid] = __ldg(a + tid);
        if (tid < 128) {
            ((float*)(smem + SM_S1B))[tid] = 0.0f;
            ((float*)(smem + SM_S2B))[tid] = 0.0f;
        }
    }

    float acc[4][4][4];
    #pragma unroll
    for (int mt = 0; mt < 4; ++mt)
        #pragma unroll
        for (int nt = 0; nt < 4; ++nt)
            #pragma unroll
            for (int j = 0; j < 4; ++j) acc[mt][nt][j] = 0.0f;

    __half* sAh = (__half*)(smem + SM_AH);
    __half* sAl = (__half*)(smem + SM_AL);
    __half* sB  = (__half*)(smem + SM_B);

    // A prefetch (registers): chunk 0
    float4 pf[8];
    #pragma unroll
    for (int it = 0; it < 8; ++it) {
        const int lin = tid + 256 * it;
        const int r = lin >> 4, j = lin & 15;
        pf[it] = make_float4(0.f, 0.f, 0.f, 0.f);
        if (row0 + r < N_NODES)
            pf[it] = *reinterpret_cast<const float4*>(
                         F + (size_t)(row0 + r) * IN_DIM + 0 * 64 + j * 4);
    }

    for (int c = 0; c < 4; ++c) {
        __syncthreads();   // previous MMA done: A/B smem free

        // store prefetched A chunk as fp16 hi+lo
        #pragma unroll
        for (int it = 0; it < 8; ++it) {
            const int lin = tid + 256 * it;
            const int r = lin >> 4, j = lin & 15;
            const float4 v = pf[it];
            __half2 h01 = __floats2half2_rn(v.x, v.y);
            __half2 h23 = __floats2half2_rn(v.z, v.w);
            __half2 l01 = __floats2half2_rn(v.x - __half2float(h01.x),
                                            v.y - __half2float(h01.y));
            __half2 l23 = __floats2half2_rn(v.z - __half2float(h23.x),
                                            v.w - __half2float(h23.y));
            *(uint2*)&sAh[r * PAD + j * 4] = make_uint2(*(uint32_t*)&h01, *(uint32_t*)&h23);
            *(uint2*)&sAl[r * PAD + j * 4] = make_uint2(*(uint32_t*)&l01, *(uint32_t*)&l23);
        }

        // B fill: W chunk c (fp32 [64k][128n], L2-hot) -> sB fp16 [128n][PAD k]
        // warp-coalesced: lanes cover consecutive n for fixed k
        {
            const int n = tid & 127;
            const int kh = (tid >> 7) * 32;
            const float* wc = W + (size_t)(c * 64 + kh) * OUT_DIM + n;
            #pragma unroll
            for (int kk = 0; kk < 32; kk += 2) {
                const float f0 = __ldg(wc + kk * OUT_DIM);
                const float f1 = __ldg(wc + (kk + 1) * OUT_DIM);
                __half2 h = __floats2half2_rn(f0, f1);
                *(uint32_t*)&sB[n * PAD + kh + kk] = *(uint32_t*)&h;
            }
        }
        __syncthreads();

        // prefetch next A chunk (LDGs overlap the MMA section below)
        if (c < 3) {
            #pragma unroll
            for (int it = 0; it < 8; ++it) {
                const int lin = tid + 256 * it;
                const int r = lin >> 4, j = lin & 15;
                pf[it] = make_float4(0.f, 0.f, 0.f, 0.f);
                if (row0 + r < N_NODES)
                    pf[it] = *reinterpret_cast<const float4*>(
                                 F + (size_t)(row0 + r) * IN_DIM + (c + 1) * 64 + j * 4);
            }
        }

        // ---- compute chunk c: 2 passes (Ah*B + Al*B)
        const int rs = lane & 7, q = lane >> 3;
        #pragma unroll
        for (int ks = 0; ks < 4; ++ks) {
            const int k0 = ks * 16;
            uint32_t ah[4][4], al[4][4];
            #pragma unroll
            for (int mt = 0; mt < 4; ++mt) {
                const int arow = warp_m * 64 + mt * 16 + rs + (q & 1) * 8;
                const int acol = k0 + (q >> 1) * 8;
                const uint32_t off = (uint32_t)(arow * PAD + acol) * 2;
                ldmx4(ah[mt], sb + SM_AH + off);
                ldmx4(al[mt], sb + SM_AL + off);
            }
            uint32_t b[2][4];
            #pragma unroll
            for (int np = 0; np < 2; ++np) {
                const int brow = warp_n * 32 + np * 16 + rs + (q >> 1) * 8;
                const int bcol = k0 + (q & 1) * 8;
                ldmx4(b[np], sb + SM_B + (uint32_t)(brow * PAD + bcol) * 2);
            }
            #pragma unroll
            for (int mt = 0; mt < 4; ++mt)
                #pragma unroll
                for (int nt = 0; nt < 4; ++nt) {
                    const uint32_t* bp = &b[nt >> 1][(nt & 1) * 2];
                    mma16816(acc[mt][nt], ah[mt], bp);   // Ah*B
                    mma16816(acc[mt][nt], al[mt], bp);   // Al*B
                }
        }
    }

    // epilogue: write h, fuse s1/s2
    const float* avec = (const float*)(smem + SM_AVEC);
    float* s1b = (float*)(smem + SM_S1B);
    float* s2b = (float*)(smem + SM_S2B);
    const int tg = lane & 3, gid = lane >> 2;

    #pragma unroll
    for (int mt = 0; mt < 4; ++mt)
        #pragma unroll
        for (int half = 0; half < 2; ++half) {
            const int rloc = warp_m * 64 + mt * 16 + half * 8 + gid;
            const int row  = row0 + rloc;
            float s1p = 0.f, s2p = 0.f;
            #pragma unroll
            for (int nt = 0; nt < 4; ++nt) {
                const float vx = acc[mt][nt][half * 2 + 0];
                const float vy = acc[mt][nt][half * 2 + 1];
                const int col = warp_n * 32 + nt * 8 + tg * 2;
                if (row < N_NODES)
                    *reinterpret_cast<float2*>(g_h + (size_t)row * OUT_DIM + col) =
                        make_float2(vx, vy);
                s1p += vx * avec[col]       + vy * avec[col + 1];
                s2p += vx * avec[128 + col] + vy * avec[128 + col + 1];
            }
            s1p += __shfl_xor_sync(0xffffffffu, s1p, 1);
            s1p += __shfl_xor_sync(0xffffffffu, s1p, 2);
            s2p += __shfl_xor_sync(0xffffffffu, s2p, 1);
            s2p += __shfl_xor_sync(0xffffffffu, s2p, 2);
            if (tg == 0) {
                atomicAdd(&s1b[rloc], s1p);
                atomicAdd(&s2b[rloc], s2p);
            }
        }
    __syncthreads();
    if (tid < 128 && row0 + tid < N_NODES) {
        g_s1[row0 + tid] = s1b[tid];
        g_s2[row0 + tid] = s2b[tid];
    }
}

// =====================================================================
// 2) per-row: hash dedup (last write wins) + softmax + float4 gather + ELU
//    (re-zeroes g_cnt[t] race-free for the next graph replay)
// =====================================================================
__global__ void __launch_bounds__(128) row_kernel(float* __restrict__ out) {
    const int t    = blockIdx.x;
    const int tid  = threadIdx.x;
    const int lane = tid & 31;
    const int wrp  = tid >> 5;

    __shared__ int   soff[CAP];       // dst * OUT_DIM (word offset into g_h)
    __shared__ float se[CAP];
    __shared__ int   sidx[CAP];
    __shared__ int   sslot[CAP];
    __shared__ int   hkey[HSZ];
    __shared__ int   hval[HSZ];
    __shared__ float wred[4];
    __shared__ float racc[4][OUT_DIM]; // per-warp gather partials

    const int k = min(g_cnt[t], CAP);
    __syncthreads();                   // all threads have read g_cnt[t]
    if (tid == 0) g_cnt[t] = 0;        // reset for next replay (deterministic)

    if (k == 0) {
        // empty row: uniform softmax -> column mean of h (P ~ 1e-24, kept for correctness)
        float s = 0.f;
        for (int row = 0; row < N_NODES; ++row)
            s += g_h[(size_t)row * OUT_DIM + tid];
        float v = s * (1.0f / (float)N_NODES);
        out[(size_t)t * OUT_DIM + tid] = (v > 0.f) ? v : expm1f(v);
        return;
    }

    // init hash table
    #pragma unroll
    for (int i = tid; i < HSZ; i += 128) { hkey[i] = -1; hval[i] = -1; }
    __syncthreads();

    // load edges (linear) + score + hash insert (winner = max edge index per dst)
    for (int i = tid; i < k; i += 128) {
        const int slot = t * CAP + i;
        const int e   = g_bucket[slot];
        const int src = g_bsrc[slot];
        const int dst = g_bdst[slot];
        sidx[i] = e;
        soff[i] = dst * OUT_DIM;
        float sc = g_s1[src] + g_s2[dst];
        se[i] = (sc > 0.f) ? sc : LRELU_ALPHA * sc;

        int h = (int)(((uint32_t)dst * 0x9E3779B1u) >> 23);   // 9 bits -> 0..511
        while (true) {
            const int cur = hkey[h];
            if (cur == dst) break;
            if (cur == -1) {
                const int old = atomicCAS(&hkey[h], -1, dst);
                if (old == -1 || old == dst) break;
            }
            h = (h + 1) & (HSZ - 1);
        }
        sslot[i] = h;
        atomicMax(&hval[h], e);
    }
    __syncthreads();

    // mark losers dead + per-thread max
    float m = -3.0e38f;
    for (int i = tid; i < k; i += 128) {
        if (hval[sslot[i]] != sidx[i]) se[i] = -3.0e38f;
        m = fmaxf(m, se[i]);
    }
    #pragma unroll
    for (int off = 16; off; off >>= 1)
        m = fmaxf(m, __shfl_xor_sync(0xffffffffu, m, off));
    if (lane == 0) wred[wrp] = m;
    __syncthreads();
    m = fmaxf(fmaxf(wred[0], wred[1]), fmaxf(wred[2], wred[3]));
    __syncthreads();

    // exp + sum
    float ssum = 0.f;
    for (int i = tid; i < k; i += 128) {
        const float w = __expf(se[i] - m);   // dead -> exactly 0
        se[i] = w;
        ssum += w;
    }
    #pragma unroll
    for (int off = 16; off; off >>= 1)
        ssum += __shfl_xor_sync(0xffffffffu, ssum, off);
    if (lane == 0) wred[wrp] = ssum;
    __syncthreads();                          // also publishes se[]/soff[] writes
    const float inv = 1.0f / (wred[0] + wred[1] + wred[2] + wred[3]);

    // float4 gather, unroll x2 (independent accumulators for MLP)
    float4 acc0 = make_float4(0.f, 0.f, 0.f, 0.f);
    float4 acc1 = make_float4(0.f, 0.f, 0.f, 0.f);
    const int colw = lane * 4;
    int i = wrp;
    for (; i + 4 < k; i += 8) {
        const float w0 = se[i], w1 = se[i + 4];
        const float4 a0 = *reinterpret_cast<const float4*>(g_h + soff[i] + colw);
        const float4 a1 = *reinterpret_cast<const float4*>(g_h + soff[i + 4] + colw);
        acc0.x += w0 * a0.x; acc0.y += w0 * a0.y; acc0.z += w0 * a0.z; acc0.w += w0 * a0.w;
        acc1.x += w1 * a1.x; acc1.y += w1 * a1.y; acc1.z += w1 * a1.z; acc1.w += w1 * a1.w;
    }
    if (i < k) {
        const float w0 = se[i];
        const float4 a0 = *reinterpret_cast<const float4*>(g_h + soff[i] + colw);
        acc0.x += w0 * a0.x; acc0.y += w0 * a0.y; acc0.z += w0 * a0.z; acc0.w += w0 * a0.w;
    }
    acc0.x += acc1.x; acc0.y += acc1.y; acc0.z += acc1.z; acc0.w += acc1.w;
    *reinterpret_cast<float4*>(&racc[wrp][colw]) = acc0;
    __syncthreads();

    const float v = (racc[0][tid] + racc[1][tid] + racc[2][tid] + racc[3][tid]) * inv;
    out[(size_t)t * OUT_DIM + tid] = (v > 0.f) ? v : expm1f(v);
}

// =====================================================================
extern "C" void kernel_launch(void* const* d_in, const int* in_sizes, int n_in,
                              void* d_out, int out_size) {
    const float* F   = (const float*)d_in[0];
    const void*  adj = d_in[1];
    const void*  tgt = d_in[2];
    const float* W   = (const float*)d_in[3];
    const float* a   = (const float*)d_in[4];
    float* out = (float*)d_out;

    static int inited = 0;
    if (!inited) {
        cudaFuncSetAttribute(gemm_mma_kernel,
                             cudaFuncAttributeMaxDynamicSharedMemorySize, SMEM_TOTAL);
        inited = 1;
    }

    gemm_mma_kernel<<<GEMM_CTAS, 256, SMEM_TOTAL>>>(F, W, a, adj, tgt);
    row_kernel<<<T_ROWS, 128>>>(out);
}

// round 13
// speedup vs baseline: 1.0914x; 1.0914x over previous
#include <cuda_runtime.h>
#include <cuda_fp16.h>
#include <math.h>
#include <stdint.h>

#define N_NODES 50000
#define IN_DIM  256
#define OUT_DIM 128
#define T_ROWS  4096
#define N_EDGES 262144
#define CAP     256
#define LRELU_ALPHA 0.2f
#define PAD 72   // fp16 elements per smem row (144B): conflict-free ldmatrix
#define HSZ 512  // dedup hash table slots (power of 2)

// ---- scratch (static __device__ globals: allocation-free) ----
__device__ float g_h[(size_t)N_NODES * OUT_DIM];   // 25.6 MB
__device__ float g_s1[N_NODES];
__device__ float g_s2[N_NODES];
__device__ int   g_cnt[T_ROWS];
__device__ int   g_bucket[T_ROWS * CAP];
__device__ int   g_bsrc[T_ROWS * CAP];
__device__ int   g_bdst[T_ROWS * CAP];
__device__ int   g_idx64;
// W^T pre-split: [128 n][256 k] fp16 hi/lo
__device__ __half g_WTh[OUT_DIM * IN_DIM];
__device__ __half g_WTl[OUT_DIM * IN_DIM];

// ---------------- helpers ----------------
__device__ __forceinline__ uint32_t smem_u32(const void* p) {
    uint32_t a;
    asm("{ .reg .u64 t; cvta.to.shared.u64 t, %1; cvt.u32.u64 %0, t; }" : "=r"(a) : "l"(p));
    return a;
}
__device__ __forceinline__ void ldmx4(uint32_t (&r)[4], uint32_t addr) {
    asm volatile("ldmatrix.sync.aligned.m8n8.x4.shared.b16 {%0,%1,%2,%3}, [%4];"
                 : "=r"(r[0]), "=r"(r[1]), "=r"(r[2]), "=r"(r[3]) : "r"(addr));
}
__device__ __forceinline__ void mma16816(float (&c)[4], const uint32_t (&a)[4],
                                         const uint32_t* b) {
    asm volatile("mma.sync.aligned.m16n8k16.row.col.f32.f16.f16.f32 "
                 "{%0,%1,%2,%3}, {%4,%5,%6,%7}, {%8,%9}, {%0,%1,%2,%3};"
                 : "+f"(c[0]), "+f"(c[1]), "+f"(c[2]), "+f"(c[3])
                 : "r"(a[0]), "r"(a[1]), "r"(a[2]), "r"(a[3]), "r"(b[0]), "r"(b[1]));
}
__device__ __forceinline__ void cp16(uint32_t dst, const void* src) {
    asm volatile("cp.async.cg.shared.global [%0], [%1], 16;" :: "r"(dst), "l"(src) : "memory");
}
#define CP_COMMIT() asm volatile("cp.async.commit_group;" ::: "memory")
#define CP_WAIT1()  asm volatile("cp.async.wait_group 1;" ::: "memory")
#define CP_WAIT0()  asm volatile("cp.async.wait_group 0;" ::: "memory")

// SMEM layout (bytes): A single-plane fp16, B hi/lo double-buffered
#define SM_AH    0                     // 18432 (128 rows x 144B)
#define SM_B0    18432                 // buf0: hi 18432 + lo 18432
#define SM_B1    55296                 // buf1
#define SM_AVEC  92160                 // 256 floats
#define SM_S1B   93184                 // 128 floats
#define SM_S2B   93696                 // 128 floats
#define SMEM_TOTAL 94208
#define B_BUF_STRIDE 36864
#define B_LO_OFF 18432

// =====================================================================
// 0) prep: W split (fp16 hi/lo) + counters + dtype sniff
// =====================================================================
__global__ void prep_kernel(const float* __restrict__ W,
                            const void* __restrict__ adj_raw) {
    const int b = blockIdx.x;
    if (b < 128) {
        const int i = b * 256 + threadIdx.x;    // 0..32767
        const int k = i >> 7, n = i & 127;
        const float v = W[i];
        __half h = __float2half_rn(v);
        __half l = __float2half_rn(v - __half2float(h));
        g_WTh[n * IN_DIM + k] = h;
        g_WTl[n * IN_DIM + k] = l;
    } else {
        const int i = (b - 128) * 256 + threadIdx.x;  // 0..4351
        if (i < T_ROWS) g_cnt[i] = 0;
        if (b == 144) {
            const int* w = (const int*)adj_raw;
            int bad = 0;
            for (int j = threadIdx.x * 2 + 1; j < 8192; j += 512)
                if (w[j] != 0) bad = 1;
            __shared__ int sbad;
            if (threadIdx.x == 0) sbad = 0;
            __syncthreads();
            if (bad) atomicOr(&sbad, 1);
            __syncthreads();
            if (threadIdx.x == 0) g_idx64 = (sbad == 0) ? 1 : 0;
        }
    }
}

// =====================================================================
// 1) HMMA GEMM: h = F@W, fp16 2-pass (A hi only; W hi+lo), fused s1/s2
// =====================================================================
__global__ void __launch_bounds__(256) gemm_mma_kernel(const float* __restrict__ F,
                                                       const float* __restrict__ a) {
    extern __shared__ char smem[];
    const uint32_t sb = smem_u32(smem);
    const int tid  = threadIdx.x;
    const int wid  = tid >> 5;
    const int lane = tid & 31;
    const int warp_m = wid & 1;
    const int warp_n = wid >> 1;
    const int row0 = blockIdx.x * 128;

    {
        float* avec = (float*)(smem + SM_AVEC);
        avec[tid] = __ldg(a + tid);
        if (tid < 128) {
            ((float*)(smem + SM_S1B))[tid] = 0.0f;
            ((float*)(smem + SM_S2B))[tid] = 0.0f;
        }
    }

    float acc[4][4][4];
    #pragma unroll
    for (int mt = 0; mt < 4; ++mt)
        #pragma unroll
        for (int nt = 0; nt < 4; ++nt)
            #pragma unroll
            for (int j = 0; j < 4; ++j) acc[mt][nt][j] = 0.0f;

    __half* sAh = (__half*)(smem + SM_AH);

    // A prefetch (registers): chunk 0
    float4 pf[8];
    #pragma unroll
    for (int it = 0; it < 8; ++it) {
        const int lin = tid + 256 * it;
        const int r = lin >> 4, j = lin & 15;
        pf[it] = make_float4(0.f, 0.f, 0.f, 0.f);
        if (row0 + r < N_NODES)
            pf[it] = *reinterpret_cast<const float4*>(
                         F + (size_t)(row0 + r) * IN_DIM + 0 * 64 + j * 4);
    }
    // B cp.async: chunk 0 -> buf 0
    {
        const uint32_t bbase = sb + SM_B0;
        #pragma unroll
        for (int it = 0; it < 4; ++it) {
            const int lin = tid + 256 * it;
            const int n = lin >> 3, j = lin & 7;
            cp16(bbase + (uint32_t)(n * PAD + j * 8) * 2,
                 &g_WTh[n * IN_DIM + 0 * 64 + j * 8]);
            cp16(bbase + B_LO_OFF + (uint32_t)(n * PAD + j * 8) * 2,
                 &g_WTl[n * IN_DIM + 0 * 64 + j * 8]);
        }
        CP_COMMIT();
    }

    for (int c = 0; c < 4; ++c) {
        __syncthreads();

        // store prefetched A chunk as fp16 (single plane)
        #pragma unroll
        for (int it = 0; it < 8; ++it) {
            const int lin = tid + 256 * it;
            const int r = lin >> 4, j = lin & 15;
            const float4 v = pf[it];
            __half2 h01 = __floats2half2_rn(v.x, v.y);
            __half2 h23 = __floats2half2_rn(v.z, v.w);
            *(uint2*)&sAh[r * PAD + j * 4] = make_uint2(*(uint32_t*)&h01, *(uint32_t*)&h23);
        }

        if (c < 3) {
            const uint32_t bbase = sb + SM_B0 + ((c + 1) & 1) * B_BUF_STRIDE;
            #pragma unroll
            for (int it = 0; it < 4; ++it) {
                const int lin = tid + 256 * it;
                const int n = lin >> 3, j = lin & 7;
                cp16(bbase + (uint32_t)(n * PAD + j * 8) * 2,
                     &g_WTh[n * IN_DIM + (c + 1) * 64 + j * 8]);
                cp16(bbase + B_LO_OFF + (uint32_t)(n * PAD + j * 8) * 2,
                     &g_WTl[n * IN_DIM + (c + 1) * 64 + j * 8]);
            }
            CP_COMMIT();
            CP_WAIT1();
        } else {
            CP_WAIT0();
        }
        __syncthreads();

        // prefetch next A chunk (overlaps MMA section)
        if (c < 3) {
            #pragma unroll
            for (int it = 0; it < 8; ++it) {
                const int lin = tid + 256 * it;
                const int r = lin >> 4, j = lin & 15;
                pf[it] = make_float4(0.f, 0.f, 0.f, 0.f);
                if (row0 + r < N_NODES)
                    pf[it] = *reinterpret_cast<const float4*>(
                                 F + (size_t)(row0 + r) * IN_DIM + (c + 1) * 64 + j * 4);
            }
        }

        // ---- compute chunk c: 2 passes (Ah*Bh + Ah*Bl)
        const uint32_t bh_off = SM_B0 + (c & 1) * B_BUF_STRIDE;
        const uint32_t bl_off = bh_off + B_LO_OFF;
        const int rs = lane & 7, q = lane >> 3;
        #pragma unroll
        for (int ks = 0; ks < 4; ++ks) {
            const int k0 = ks * 16;
            uint32_t ah[4][4];
            #pragma unroll
            for (int mt = 0; mt < 4; ++mt) {
                const int arow = warp_m * 64 + mt * 16 + rs + (q & 1) * 8;
                const int acol = k0 + (q >> 1) * 8;
                ldmx4(ah[mt], sb + SM_AH + (uint32_t)(arow * PAD + acol) * 2);
            }
            uint32_t bh[2][4], bl[2][4];
            #pragma unroll
            for (int np = 0; np < 2; ++np) {
                const int brow = warp_n * 32 + np * 16 + rs + (q >> 1) * 8;
                const int bcol = k0 + (q & 1) * 8;
                const uint32_t off = (uint32_t)(brow * PAD + bcol) * 2;
                ldmx4(bh[np], sb + bh_off + off);
                ldmx4(bl[np], sb + bl_off + off);
            }
            #pragma unroll
            for (int mt = 0; mt < 4; ++mt)
                #pragma unroll
                for (int nt = 0; nt < 4; ++nt) {
                    const uint32_t* bhp = &bh[nt >> 1][(nt & 1) * 2];
                    const uint32_t* blp = &bl[nt >> 1][(nt & 1) * 2];
                    mma16816(acc[mt][nt], ah[mt], bhp);   // Ah*Bh
                    mma16816(acc[mt][nt], ah[mt], blp);   // Ah*Bl
                }
        }
    }

    // epilogue: write h, fuse s1/s2
    const float* avec = (const float*)(smem + SM_AVEC);
    float* s1b = (float*)(smem + SM_S1B);
    float* s2b = (float*)(smem + SM_S2B);
    const int tg = lane & 3, gid = lane >> 2;

    #pragma unroll
    for (int mt = 0; mt < 4; ++mt)
        #pragma unroll
        for (int half = 0; half < 2; ++half) {
            const int rloc = warp_m * 64 + mt * 16 + half * 8 + gid;
            const int row  = row0 + rloc;
            float s1p = 0.f, s2p = 0.f;
            #pragma unroll
            for (int nt = 0; nt < 4; ++nt) {
                const float vx = acc[mt][nt][half * 2 + 0];
                const float vy = acc[mt][nt][half * 2 + 1];
                const int col = warp_n * 32 + nt * 8 + tg * 2;
                if (row < N_NODES)
                    *reinterpret_cast<float2*>(g_h + (size_t)row * OUT_DIM + col) =
                        make_float2(vx, vy);
                s1p += vx * avec[col]       + vy * avec[col + 1];
                s2p += vx * avec[128 + col] + vy * avec[128 + col + 1];
            }
            s1p += __shfl_xor_sync(0xffffffffu, s1p, 1);
            s1p += __shfl_xor_sync(0xffffffffu, s1p, 2);
            s2p += __shfl_xor_sync(0xffffffffu, s2p, 1);
            s2p += __shfl_xor_sync(0xffffffffu, s2p, 2);
            if (tg == 0) {
                atomicAdd(&s1b[rloc], s1p);
                atomicAdd(&s2b[rloc], s2p);
            }
        }
    __syncthreads();
    if (tid < 128 && row0 + tid < N_NODES) {
        g_s1[row0 + tid] = s1b[tid];
        g_s2[row0 + tid] = s2b[tid];
    }
}

// =====================================================================
// 2) per-edge bucketing: decode adj here (hidden under GEMM)
// =====================================================================
__global__ void __launch_bounds__(256) edge_kernel(const void* __restrict__ adj_raw,
                                                   const void* __restrict__ tgt_raw) {
    const int base = blockIdx.x * 256 + threadIdx.x;
    const int is64 = g_idx64;
    int t[4], sr[4], ds[4];
    #pragma unroll
    for (int u = 0; u < 4; ++u) {
        const int i = base + u * 65536;
        if (is64) {
            t[u]  = (int)((const long long*)tgt_raw)[i];
            sr[u] = (int)((const long long*)adj_raw)[i];
            ds[u] = (int)((const long long*)adj_raw)[N_EDGES + i];
        } else {
            t[u]  = ((const int*)tgt_raw)[i];
            sr[u] = ((const int*)adj_raw)[i];
            ds[u] = ((const int*)adj_raw)[N_EDGES + i];
        }
    }
    int p[4];
    #pragma unroll
    for (int u = 0; u < 4; ++u) p[u] = atomicAdd(&g_cnt[t[u]], 1);
    #pragma unroll
    for (int u = 0; u < 4; ++u)
        if (p[u] < CAP) {
            const int slot = t[u] * CAP + p[u];
            g_bucket[slot] = base + u * 65536;
            g_bsrc[slot]   = sr[u];
            g_bdst[slot]   = ds[u];
        }
}

// =====================================================================
// 3) per-row: hash dedup (last write wins) + softmax + float4 gather + ELU
// =====================================================================
__global__ void __launch_bounds__(128) row_kernel(float* __restrict__ out) {
    const int t    = blockIdx.x;
    const int tid  = threadIdx.x;
    const int lane = tid & 31;
    const int wrp  = tid >> 5;

    __shared__ int   soff[CAP];       // dst * OUT_DIM (word offset into g_h)
    __shared__ float se[CAP];
    __shared__ int   sidx[CAP];
    __shared__ int   sslot[CAP];
    __shared__ int   hkey[HSZ];
    __shared__ int   hval[HSZ];
    __shared__ float wred[4];
    __shared__ float racc[4][OUT_DIM]; // per-warp gather partials

    const int k = min(g_cnt[t], CAP);

    if (k == 0) {
        // empty row: uniform softmax -> column mean of h (P ~ 1e-24, kept for correctness)
        float s = 0.f;
        for (int row = 0; row < N_NODES; ++row)
            s += g_h[(size_t)row * OUT_DIM + tid];
        float v = s * (1.0f / (float)N_NODES);
        out[(size_t)t * OUT_DIM + tid] = (v > 0.f) ? v : expm1f(v);
        return;
    }

    // init hash table
    #pragma unroll
    for (int i = tid; i < HSZ; i += 128) { hkey[i] = -1; hval[i] = -1; }
    __syncthreads();

    // load edges (linear) + score + hash insert (winner = max edge index per dst)
    for (int i = tid; i < k; i += 128) {
        const int slot = t * CAP + i;
        const int e   = g_bucket[slot];
        const int src = g_bsrc[slot];
        const int dst = g_bdst[slot];
        sidx[i] = e;
        soff[i] = dst * OUT_DIM;
        float sc = g_s1[src] + g_s2[dst];
        se[i] = (sc > 0.f) ? sc : LRELU_ALPHA * sc;

        int h = (int)(((uint32_t)dst * 0x9E3779B1u) >> 23);   // 9 bits -> 0..511
        while (true) {
            const int cur = hkey[h];
            if (cur == dst) break;
            if (cur == -1) {
                const int old = atomicCAS(&hkey[h], -1, dst);
                if (old == -1 || old == dst) break;
            }
            h = (h + 1) & (HSZ - 1);
        }
        sslot[i] = h;
        atomicMax(&hval[h], e);
    }
    __syncthreads();

    // mark losers dead + per-thread max
    float m = -3.0e38f;
    for (int i = tid; i < k; i += 128) {
        if (hval[sslot[i]] != sidx[i]) se[i] = -3.0e38f;
        m = fmaxf(m, se[i]);
    }
    #pragma unroll
    for (int off = 16; off; off >>= 1)
        m = fmaxf(m, __shfl_xor_sync(0xffffffffu, m, off));
    if (lane == 0) wred[wrp] = m;
    __syncthreads();
    m = fmaxf(fmaxf(wred[0], wred[1]), fmaxf(wred[2], wred[3]));
    __syncthreads();

    // exp + sum
    float ssum = 0.f;
    for (int i = tid; i < k; i += 128) {
        const float w = __expf(se[i] - m);   // dead -> exactly 0
        se[i] = w;
        ssum += w;
    }
    #pragma unroll
    for (int off = 16; off; off >>= 1)
        ssum += __shfl_xor_sync(0xffffffffu, ssum, off);
    if (lane == 0) wred[wrp] = ssum;
    __syncthreads();                          // also publishes se[]/soff[] writes
    const float inv = 1.0f / (wred[0] + wred[1] + wred[2] + wred[3]);

    // float4 gather, unroll x2 (independent accumulators for MLP)
    float4 acc0 = make_float4(0.f, 0.f, 0.f, 0.f);
    float4 acc1 = make_float4(0.f, 0.f, 0.f, 0.f);
    const int colw = lane * 4;
    int i = wrp;
    for (; i + 4 < k; i += 8) {
        const float w0 = se[i], w1 = se[i + 4];
        const float4 a0 = *reinterpret_cast<const float4*>(g_h + soff[i] + colw);
        const float4 a1 = *reinterpret_cast<const float4*>(g_h + soff[i + 4] + colw);
        acc0.x += w0 * a0.x; acc0.y += w0 * a0.y; acc0.z += w0 * a0.z; acc0.w += w0 * a0.w;
        acc1.x += w1 * a1.x; acc1.y += w1 * a1.y; acc1.z += w1 * a1.z; acc1.w += w1 * a1.w;
    }
    if (i < k) {
        const float w0 = se[i];
        const float4 a0 = *reinterpret_cast<const float4*>(g_h + soff[i] + colw);
        acc0.x += w0 * a0.x; acc0.y += w0 * a0.y; acc0.z += w0 * a0.z; acc0.w += w0 * a0.w;
    }
    acc0.x += acc1.x; acc0.y += acc1.y; acc0.z += acc1.z; acc0.w += acc1.w;
    *reinterpret_cast<float4*>(&racc[wrp][colw]) = acc0;
    __syncthreads();

    const float v = (racc[0][tid] + racc[1][tid] + racc[2][tid] + racc[3][tid]) * inv;
    out[(size_t)t * OUT_DIM + tid] = (v > 0.f) ? v : expm1f(v);
}

// =====================================================================
extern "C" void kernel_launch(void* const* d_in, const int* in_sizes, int n_in,
                              void* d_out, int out_size) {
    const float* F   = (const float*)d_in[0];
    const void*  adj = d_in[1];
    const void*  tgt = d_in[2];
    const float* W   = (const float*)d_in[3];
    const float* a   = (const float*)d_in[4];
    float* out = (float*)d_out;

    static cudaStream_t s2 = nullptr;
    static cudaEvent_t  ev_fork = nullptr, ev_join = nullptr;
    static int inited = 0;
    if (!inited) {
        cudaFuncSetAttribute(gemm_mma_kernel,
                             cudaFuncAttributeMaxDynamicSharedMemorySize, SMEM_TOTAL);
        cudaStreamCreateWithFlags(&s2, cudaStreamNonBlocking);
        cudaEventCreateWithFlags(&ev_fork, cudaEventDisableTiming);
        cudaEventCreateWithFlags(&ev_join, cudaEventDisableTiming);
        inited = 1;
    }

    // main stream: prep -> gemm ; side stream: edge (bucketing + adj decode)
    prep_kernel<<<145, 256>>>(W, adj);
    cudaEventRecord(ev_fork, 0);
    cudaStreamWaitEvent(s2, ev_fork, 0);

    gemm_mma_kernel<<<(N_NODES + 127) / 128, 256, SMEM_TOTAL>>>(F, a);
    edge_kernel<<<256, 256, 0, s2>>>(adj, tgt);
    cudaEventRecord(ev_join, s2);

    cudaStreamWaitEvent(0, ev_join, 0);
    row_kernel<<<T_ROWS, 128>>>(out);
}

// round 14
// speedup vs baseline: 1.0919x; 1.0005x over previous
#include <cuda_runtime.h>
#include <cuda_fp16.h>
#include <math.h>
#include <stdint.h>

#define N_NODES 50000
#define IN_DIM  256
#define OUT_DIM 128
#define T_ROWS  4096
#define N_EDGES 262144
#define CAP     256
#define LRELU_ALPHA 0.2f
#define PAD 72   // fp16 elements per smem row (144B): conflict-free ldmatrix
#define HSZ 512  // dedup hash table slots (power of 2)

// ---- scratch (static __device__ globals: allocation-free) ----
__device__ float g_h[(size_t)N_NODES * OUT_DIM];   // 25.6 MB
__device__ float g_s1[N_NODES];
__device__ float g_s2[N_NODES];
__device__ int   g_cnt[T_ROWS];
__device__ int   g_bucket[T_ROWS * CAP];
__device__ int   g_bsrc[T_ROWS * CAP];
__device__ int   g_bdst[T_ROWS * CAP];
__device__ int   g_idx64;
// W^T pre-split: [128 n][256 k] fp16 hi/lo
__device__ __half g_WTh[OUT_DIM * IN_DIM];
__device__ __half g_WTl[OUT_DIM * IN_DIM];

// ---------------- helpers ----------------
__device__ __forceinline__ uint32_t smem_u32(const void* p) {
    uint32_t a;
    asm("{ .reg .u64 t; cvta.to.shared.u64 t, %1; cvt.u32.u64 %0, t; }" : "=r"(a) : "l"(p));
    return a;
}
__device__ __forceinline__ void ldmx4(uint32_t (&r)[4], uint32_t addr) {
    asm volatile("ldmatrix.sync.aligned.m8n8.x4.shared.b16 {%0,%1,%2,%3}, [%4];"
                 : "=r"(r[0]), "=r"(r[1]), "=r"(r[2]), "=r"(r[3]) : "r"(addr));
}
__device__ __forceinline__ void mma16816(float (&c)[4], const uint32_t (&a)[4],
                                         const uint32_t* b) {
    asm volatile("mma.sync.aligned.m16n8k16.row.col.f32.f16.f16.f32 "
                 "{%0,%1,%2,%3}, {%4,%5,%6,%7}, {%8,%9}, {%0,%1,%2,%3};"
                 : "+f"(c[0]), "+f"(c[1]), "+f"(c[2]), "+f"(c[3])
                 : "r"(a[0]), "r"(a[1]), "r"(a[2]), "r"(a[3]), "r"(b[0]), "r"(b[1]));
}
__device__ __forceinline__ void cp16(uint32_t dst, const void* src) {
    asm volatile("cp.async.cg.shared.global [%0], [%1], 16;" :: "r"(dst), "l"(src) : "memory");
}
#define CP_COMMIT() asm volatile("cp.async.commit_group;" ::: "memory")
#define CP_WAIT1()  asm volatile("cp.async.wait_group 1;" ::: "memory")
#define CP_WAIT0()  asm volatile("cp.async.wait_group 0;" ::: "memory")

// SMEM layout (bytes): A single-plane fp16, B hi/lo double-buffered
#define SM_AH    0                     // 18432 (128 rows x 144B)
#define SM_B0    18432                 // buf0: hi 18432 + lo 18432
#define SM_B1    55296                 // buf1
#define SM_AVEC  92160                 // 256 floats
#define SM_S1B   93184                 // 128 floats
#define SM_S2B   93696                 // 128 floats
#define SMEM_TOTAL 94208
#define B_BUF_STRIDE 36864
#define B_LO_OFF 18432

// =====================================================================
// 0) prep: W split (fp16 hi/lo) + counters + dtype sniff
// =====================================================================
__global__ void prep_kernel(const float* __restrict__ W,
                            const void* __restrict__ adj_raw) {
    const int b = blockIdx.x;
    if (b < 128) {
        const int i = b * 256 + threadIdx.x;    // 0..32767
        const int k = i >> 7, n = i & 127;
        const float v = W[i];
        __half h = __float2half_rn(v);
        __half l = __float2half_rn(v - __half2float(h));
        g_WTh[n * IN_DIM + k] = h;
        g_WTl[n * IN_DIM + k] = l;
    } else {
        const int i = (b - 128) * 256 + threadIdx.x;  // 0..4351
        if (i < T_ROWS) g_cnt[i] = 0;
        if (b == 144) {
            const int* w = (const int*)adj_raw;
            int bad = 0;
            for (int j = threadIdx.x * 2 + 1; j < 8192; j += 512)
                if (w[j] != 0) bad = 1;
            __shared__ int sbad;
            if (threadIdx.x == 0) sbad = 0;
            __syncthreads();
            if (bad) atomicOr(&sbad, 1);
            __syncthreads();
            if (threadIdx.x == 0) g_idx64 = (sbad == 0) ? 1 : 0;
        }
    }
}

// =====================================================================
// 1) HMMA GEMM: h = F@W, fp16 2-pass (A hi only; W hi+lo), fused s1/s2
// =====================================================================
__global__ void __launch_bounds__(256) gemm_mma_kernel(const float* __restrict__ F,
                                                       const float* __restrict__ a) {
    extern __shared__ char smem[];
    const uint32_t sb = smem_u32(smem);
    const int tid  = threadIdx.x;
    const int wid  = tid >> 5;
    const int lane = tid & 31;
    const int warp_m = wid & 1;
    const int warp_n = wid >> 1;
    const int row0 = blockIdx.x * 128;

    {
        float* avec = (float*)(smem + SM_AVEC);
        avec[tid] = __ldg(a + tid);
        if (tid < 128) {
            ((float*)(smem + SM_S1B))[tid] = 0.0f;
            ((float*)(smem + SM_S2B))[tid] = 0.0f;
        }
    }

    float acc[4][4][4];
    #pragma unroll
    for (int mt = 0; mt < 4; ++mt)
        #pragma unroll
        for (int nt = 0; nt < 4; ++nt)
            #pragma unroll
            for (int j = 0; j < 4; ++j) acc[mt][nt][j] = 0.0f;

    __half* sAh = (__half*)(smem + SM_AH);

    // A prefetch (registers): chunk 0
    float4 pf[8];
    #pragma unroll
    for (int it = 0; it < 8; ++it) {
        const int lin = tid + 256 * it;
        const int r = lin >> 4, j = lin & 15;
        pf[it] = make_float4(0.f, 0.f, 0.f, 0.f);
        if (row0 + r < N_NODES)
            pf[it] = *reinterpret_cast<const float4*>(
                         F + (size_t)(row0 + r) * IN_DIM + 0 * 64 + j * 4);
    }
    // B cp.async: chunk 0 -> buf 0
    {
        const uint32_t bbase = sb + SM_B0;
        #pragma unroll
        for (int it = 0; it < 4; ++it) {
            const int lin = tid + 256 * it;
            const int n = lin >> 3, j = lin & 7;
            cp16(bbase + (uint32_t)(n * PAD + j * 8) * 2,
                 &g_WTh[n * IN_DIM + 0 * 64 + j * 8]);
            cp16(bbase + B_LO_OFF + (uint32_t)(n * PAD + j * 8) * 2,
                 &g_WTl[n * IN_DIM + 0 * 64 + j * 8]);
        }
        CP_COMMIT();
    }

    for (int c = 0; c < 4; ++c) {
        __syncthreads();

        // store prefetched A chunk as fp16 (single plane)
        #pragma unroll
        for (int it = 0; it < 8; ++it) {
            const int lin = tid + 256 * it;
            const int r = lin >> 4, j = lin & 15;
            const float4 v = pf[it];
            __half2 h01 = __floats2half2_rn(v.x, v.y);
            __half2 h23 = __floats2half2_rn(v.z, v.w);
            *(uint2*)&sAh[r * PAD + j * 4] = make_uint2(*(uint32_t*)&h01, *(uint32_t*)&h23);
        }

        if (c < 3) {
            const uint32_t bbase = sb + SM_B0 + ((c + 1) & 1) * B_BUF_STRIDE;
            #pragma unroll
            for (int it = 0; it < 4; ++it) {
                const int lin = tid + 256 * it;
                const int n = lin >> 3, j = lin & 7;
                cp16(bbase + (uint32_t)(n * PAD + j * 8) * 2,
                     &g_WTh[n * IN_DIM + (c + 1) * 64 + j * 8]);
                cp16(bbase + B_LO_OFF + (uint32_t)(n * PAD + j * 8) * 2,
                     &g_WTl[n * IN_DIM + (c + 1) * 64 + j * 8]);
            }
            CP_COMMIT();
            CP_WAIT1();
        } else {
            CP_WAIT0();
        }
        __syncthreads();

        // prefetch next A chunk (overlaps MMA section)
        if (c < 3) {
            #pragma unroll
            for (int it = 0; it < 8; ++it) {
                const int lin = tid + 256 * it;
                const int r = lin >> 4, j = lin & 15;
                pf[it] = make_float4(0.f, 0.f, 0.f, 0.f);
                if (row0 + r < N_NODES)
                    pf[it] = *reinterpret_cast<const float4*>(
                                 F + (size_t)(row0 + r) * IN_DIM + (c + 1) * 64 + j * 4);
            }
        }

        // ---- compute chunk c: 2 passes (Ah*Bh + Ah*Bl)
        const uint32_t bh_off = SM_B0 + (c & 1) * B_BUF_STRIDE;
        const uint32_t bl_off = bh_off + B_LO_OFF;
        const int rs = lane & 7, q = lane >> 3;
        #pragma unroll
        for (int ks = 0; ks < 4; ++ks) {
            const int k0 = ks * 16;
            uint32_t ah[4][4];
            #pragma unroll
            for (int mt = 0; mt < 4; ++mt) {
                const int arow = warp_m * 64 + mt * 16 + rs + (q & 1) * 8;
                const int acol = k0 + (q >> 1) * 8;
                ldmx4(ah[mt], sb + SM_AH + (uint32_t)(arow * PAD + acol) * 2);
            }
            uint32_t bh[2][4], bl[2][4];
            #pragma unroll
            for (int np = 0; np < 2; ++np) {
                const int brow = warp_n * 32 + np * 16 + rs + (q >> 1) * 8;
                const int bcol = k0 + (q & 1) * 8;
                const uint32_t off = (uint32_t)(brow * PAD + bcol) * 2;
                ldmx4(bh[np], sb + bh_off + off);
                ldmx4(bl[np], sb + bl_off + off);
            }
            #pragma unroll
            for (int mt = 0; mt < 4; ++mt)
                #pragma unroll
                for (int nt = 0; nt < 4; ++nt) {
                    const uint32_t* bhp = &bh[nt >> 1][(nt & 1) * 2];
                    const uint32_t* blp = &bl[nt >> 1][(nt & 1) * 2];
                    mma16816(acc[mt][nt], ah[mt], bhp);   // Ah*Bh
                    mma16816(acc[mt][nt], ah[mt], blp);   // Ah*Bl
                }
        }
    }

    // epilogue: write h, fuse s1/s2
    const float* avec = (const float*)(smem + SM_AVEC);
    float* s1b = (float*)(smem + SM_S1B);
    float* s2b = (float*)(smem + SM_S2B);
    const int tg = lane & 3, gid = lane >> 2;

    #pragma unroll
    for (int mt = 0; mt < 4; ++mt)
        #pragma unroll
        for (int half = 0; half < 2; ++half) {
            const int rloc = warp_m * 64 + mt * 16 + half * 8 + gid;
            const int row  = row0 + rloc;
            float s1p = 0.f, s2p = 0.f;
            #pragma unroll
            for (int nt = 0; nt < 4; ++nt) {
                const float vx = acc[mt][nt][half * 2 + 0];
                const float vy = acc[mt][nt][half * 2 + 1];
                const int col = warp_n * 32 + nt * 8 + tg * 2;
                if (row < N_NODES)
                    *reinterpret_cast<float2*>(g_h + (size_t)row * OUT_DIM + col) =
                        make_float2(vx, vy);
                s1p += vx * avec[col]       + vy * avec[col + 1];
                s2p += vx * avec[128 + col] + vy * avec[128 + col + 1];
            }
            s1p += __shfl_xor_sync(0xffffffffu, s1p, 1);
            s1p += __shfl_xor_sync(0xffffffffu, s1p, 2);
            s2p += __shfl_xor_sync(0xffffffffu, s2p, 1);
            s2p += __shfl_xor_sync(0xffffffffu, s2p, 2);
            if (tg == 0) {
                atomicAdd(&s1b[rloc], s1p);
                atomicAdd(&s2b[rloc], s2p);
            }
        }
    __syncthreads();
    if (tid < 128 && row0 + tid < N_NODES) {
        g_s1[row0 + tid] = s1b[tid];
        g_s2[row0 + tid] = s2b[tid];
    }
}

// =====================================================================
// 2) per-edge bucketing: decode adj here (hidden under GEMM)
// =====================================================================
__global__ void __launch_bounds__(256) edge_kernel(const void* __restrict__ adj_raw,
                                                   const void* __restrict__ tgt_raw) {
    const int base = blockIdx.x * 256 + threadIdx.x;
    const int is64 = g_idx64;
    int t[4], sr[4], ds[4];
    #pragma unroll
    for (int u = 0; u < 4; ++u) {
        const int i = base + u * 65536;
        if (is64) {
            t[u]  = (int)((const long long*)tgt_raw)[i];
            sr[u] = (int)((const long long*)adj_raw)[i];
            ds[u] = (int)((const long long*)adj_raw)[N_EDGES + i];
        } else {
            t[u]  = ((const int*)tgt_raw)[i];
            sr[u] = ((const int*)adj_raw)[i];
            ds[u] = ((const int*)adj_raw)[N_EDGES + i];
        }
    }
    int p[4];
    #pragma unroll
    for (int u = 0; u < 4; ++u) p[u] = atomicAdd(&g_cnt[t[u]], 1);
    #pragma unroll
    for (int u = 0; u < 4; ++u)
        if (p[u] < CAP) {
            const int slot = t[u] * CAP + p[u];
            g_bucket[slot] = base + u * 65536;
            g_bsrc[slot]   = sr[u];
            g_bdst[slot]   = ds[u];
        }
}

// =====================================================================
// 3) per-row: hash dedup (last write wins) + softmax + float4 gather + ELU
// =====================================================================
__global__ void __launch_bounds__(128) row_kernel(float* __restrict__ out) {
    const int t    = blockIdx.x;
    const int tid  = threadIdx.x;
    const int lane = tid & 31;
    const int wrp  = tid >> 5;

    __shared__ int   soff[CAP];       // dst * OUT_DIM (word offset into g_h)
    __shared__ float se[CAP];
    __shared__ int   sidx[CAP];
    __shared__ int   sslot[CAP];
    __shared__ int   hkey[HSZ];
    __shared__ int   hval[HSZ];
    __shared__ float wred[4];
    __shared__ float racc[4][OUT_DIM]; // per-warp gather partials

    const int k = min(g_cnt[t], CAP);

    if (k == 0) {
        // empty row: uniform softmax -> column mean of h (P ~ 1e-24, kept for correctness)
        float s = 0.f;
        for (int row = 0; row < N_NODES; ++row)
            s += g_h[(size_t)row * OUT_DIM + tid];
        float v = s * (1.0f / (float)N_NODES);
        out[(size_t)t * OUT_DIM + tid] = (v > 0.f) ? v : expm1f(v);
        return;
    }

    // init hash table
    #pragma unroll
    for (int i = tid; i < HSZ; i += 128) { hkey[i] = -1; hval[i] = -1; }
    __syncthreads();

    // load edges (linear) + score + hash insert (winner = max edge index per dst)
    for (int i = tid; i < k; i += 128) {
        const int slot = t * CAP + i;
        const int e   = g_bucket[slot];
        const int src = g_bsrc[slot];
        const int dst = g_bdst[slot];
        sidx[i] = e;
        soff[i] = dst * OUT_DIM;
        float sc = g_s1[src] + g_s2[dst];
        se[i] = (sc > 0.f) ? sc : LRELU_ALPHA * sc;

        int h = (int)(((uint32_t)dst * 0x9E3779B1u) >> 23);   // 9 bits -> 0..511
        while (true) {
            const int cur = hkey[h];
            if (cur == dst) break;
            if (cur == -1) {
                const int old = atomicCAS(&hkey[h], -1, dst);
                if (old == -1 || old == dst) break;
            }
            h = (h + 1) & (HSZ - 1);
        }
        sslot[i] = h;
        atomicMax(&hval[h], e);
    }
    __syncthreads();

    // mark losers dead + per-thread max
    float m = -3.0e38f;
    for (int i = tid; i < k; i += 128) {
        if (hval[sslot[i]] != sidx[i]) se[i] = -3.0e38f;
        m = fmaxf(m, se[i]);
    }
    #pragma unroll
    for (int off = 16; off; off >>= 1)
        m = fmaxf(m, __shfl_xor_sync(0xffffffffu, m, off));
    if (lane == 0) wred[wrp] = m;
    __syncthreads();
    m = fmaxf(fmaxf(wred[0], wred[1]), fmaxf(wred[2], wred[3]));
    __syncthreads();

    // exp + sum
    float ssum = 0.f;
    for (int i = tid; i < k; i += 128) {
        const float w = __expf(se[i] - m);   // dead -> exactly 0
        se[i] = w;
        ssum += w;
    }
    #pragma unroll
    for (int off = 16; off; off >>= 1)
        ssum += __shfl_xor_sync(0xffffffffu, ssum, off);
    if (lane == 0) wred[wrp] = ssum;
    __syncthreads();                          // also publishes se[]/soff[] writes
    const float inv = 1.0f / (wred[0] + wred[1] + wred[2] + wred[3]);

    // float4 gather, unroll x2 (independent accumulators for MLP)
    float4 acc0 = make_float4(0.f, 0.f, 0.f, 0.f);
    float4 acc1 = make_float4(0.f, 0.f, 0.f, 0.f);
    const int colw = lane * 4;
    int i = wrp;
    for (; i + 4 < k; i += 8) {
        const float w0 = se[i], w1 = se[i + 4];
        const float4 a0 = *reinterpret_cast<const float4*>(g_h + soff[i] + colw);
        const float4 a1 = *reinterpret_cast<const float4*>(g_h + soff[i + 4] + colw);
        acc0.x += w0 * a0.x; acc0.y += w0 * a0.y; acc0.z += w0 * a0.z; acc0.w += w0 * a0.w;
        acc1.x += w1 * a1.x; acc1.y += w1 * a1.y; acc1.z += w1 * a1.z; acc1.w += w1 * a1.w;
    }
    if (i < k) {
        const float w0 = se[i];
        const float4 a0 = *reinterpret_cast<const float4*>(g_h + soff[i] + colw);
        acc0.x += w0 * a0.x; acc0.y += w0 * a0.y; acc0.z += w0 * a0.z; acc0.w += w0 * a0.w;
    }
    acc0.x += acc1.x; acc0.y += acc1.y; acc0.z += acc1.z; acc0.w += acc1.w;
    *reinterpret_cast<float4*>(&racc[wrp][colw]) = acc0;
    __syncthreads();

    const float v = (racc[0][tid] + racc[1][tid] + racc[2][tid] + racc[3][tid]) * inv;
    out[(size_t)t * OUT_DIM + tid] = (v > 0.f) ? v : expm1f(v);
}

// =====================================================================
extern "C" void kernel_launch(void* const* d_in, const int* in_sizes, int n_in,
                              void* d_out, int out_size) {
    const float* F   = (const float*)d_in[0];
    const void*  adj = d_in[1];
    const void*  tgt = d_in[2];
    const float* W   = (const float*)d_in[3];
    const float* a   = (const float*)d_in[4];
    float* out = (float*)d_out;

    static cudaStream_t s2 = nullptr;
    static cudaEvent_t  ev_fork = nullptr, ev_join = nullptr;
    static int inited = 0;
    if (!inited) {
        cudaFuncSetAttribute(gemm_mma_kernel,
                             cudaFuncAttributeMaxDynamicSharedMemorySize, SMEM_TOTAL);
        cudaStreamCreateWithFlags(&s2, cudaStreamNonBlocking);
        cudaEventCreateWithFlags(&ev_fork, cudaEventDisableTiming);
        cudaEventCreateWithFlags(&ev_join, cudaEventDisableTiming);
        inited = 1;
    }

    // main stream: prep -> gemm ; side stream: edge (bucketing + adj decode)
    prep_kernel<<<145, 256>>>(W, adj);
    cudaEventRecord(ev_fork, 0);
    cudaStreamWaitEvent(s2, ev_fork, 0);

    gemm_mma_kernel<<<(N_NODES + 127) / 128, 256, SMEM_TOTAL>>>(F, a);
    edge_kernel<<<256, 256, 0, s2>>>(adj, tgt);
    cudaEventRecord(ev_join, s2);

    cudaStreamWaitEvent(0, ev_join, 0);
    row_kernel<<<T_ROWS, 128>>>(out);
}